// round 1
// baseline (speedup 1.0000x reference)
#include <cuda_runtime.h>

// SyntheticTripletLoss: loss = mean over valid (b,t) of
//   max(MARGIN + sim_pn - sim_pt, 0)
// where sim_pt = <p,t>, neg = normalize(p - sim_pt * t),
//   sim_pn = <p, neg> = (<p,p> - sim_pt^2) / max(||p - sim_pt t||, EPS)
// Closed form needs only pp, tt, pt per row.

#define MARGIN 0.5f
#define EPS_N 1e-12f

static constexpr int B = 32;
static constexpr int T = 512;
static constexpr int D = 512;
static constexpr int WARPS_PER_BLOCK = 8;
static constexpr int ROWS = B * T;                      // 16384
static constexpr int NBLOCKS = ROWS / WARPS_PER_BLOCK;  // 2048

__device__ float g_partials[NBLOCKS];

__global__ __launch_bounds__(WARPS_PER_BLOCK * 32)
void triplet_rows_kernel(const float* __restrict__ preds,
                         const float* __restrict__ targets,
                         const int* __restrict__ lengths) {
    const int warp = threadIdx.x >> 5;
    const int lane = threadIdx.x & 31;
    const int row  = blockIdx.x * WARPS_PER_BLOCK + warp;
    const int b    = row >> 9;        // row / T
    const int t    = row & (T - 1);   // row % T

    float loss = 0.0f;

    if (t < __ldg(&lengths[b])) {
        const float4* __restrict__ p4 =
            reinterpret_cast<const float4*>(preds + (size_t)row * D);
        const float4* __restrict__ t4 =
            reinterpret_cast<const float4*>(targets + (size_t)row * D);

        // 512 floats / 32 lanes = 16 floats = 4 float4 per lane per tensor.
        // Issue all 8 loads up front for MLP, then accumulate.
        float4 a0 = __ldg(p4 + lane);
        float4 a1 = __ldg(p4 + lane + 32);
        float4 a2 = __ldg(p4 + lane + 64);
        float4 a3 = __ldg(p4 + lane + 96);
        float4 c0 = __ldg(t4 + lane);
        float4 c1 = __ldg(t4 + lane + 32);
        float4 c2 = __ldg(t4 + lane + 64);
        float4 c3 = __ldg(t4 + lane + 96);

        float pp = 0.f, tt = 0.f, pt = 0.f;
        #define ACC(a, c)                                                  \
            pp = fmaf(a.x, a.x, fmaf(a.y, a.y, fmaf(a.z, a.z, fmaf(a.w, a.w, pp)))); \
            tt = fmaf(c.x, c.x, fmaf(c.y, c.y, fmaf(c.z, c.z, fmaf(c.w, c.w, tt)))); \
            pt = fmaf(a.x, c.x, fmaf(a.y, c.y, fmaf(a.z, c.z, fmaf(a.w, c.w, pt))));
        ACC(a0, c0) ACC(a1, c1) ACC(a2, c2) ACC(a3, c3)
        #undef ACC

        #pragma unroll
        for (int off = 16; off; off >>= 1) {
            pp += __shfl_xor_sync(0xffffffffu, pp, off);
            tt += __shfl_xor_sync(0xffffffffu, tt, off);
            pt += __shfl_xor_sync(0xffffffffu, pt, off);
        }

        float pt2  = pt * pt;
        float n2   = fmaxf(pp - 2.0f * pt2 + pt2 * tt, 0.0f);
        float norm = fmaxf(sqrtf(n2), EPS_N);
        float sim_pn = (pp - pt2) / norm;
        loss = fmaxf(MARGIN + sim_pn - pt, 0.0f);
    }

    __shared__ float s_warp[WARPS_PER_BLOCK];
    if (lane == 0) s_warp[warp] = loss;
    __syncthreads();
    if (threadIdx.x == 0) {
        float sum = 0.f;
        #pragma unroll
        for (int i = 0; i < WARPS_PER_BLOCK; i++) sum += s_warp[i];
        g_partials[blockIdx.x] = sum;  // deterministic: fixed slot per block
    }
}

__global__ __launch_bounds__(256)
void finalize_kernel(const int* __restrict__ lengths, float* __restrict__ out) {
    __shared__ float s[256];
    float sum = 0.f;
    for (int i = threadIdx.x; i < NBLOCKS; i += 256) sum += g_partials[i];
    s[threadIdx.x] = sum;
    __syncthreads();
    #pragma unroll
    for (int off = 128; off; off >>= 1) {
        if (threadIdx.x < off) s[threadIdx.x] += s[threadIdx.x + off];
        __syncthreads();
    }
    if (threadIdx.x == 0) {
        int cnt = 0;
        #pragma unroll
        for (int i = 0; i < B; i++) cnt += __ldg(&lengths[i]);
        out[0] = s[0] / (float)cnt;
    }
}

extern "C" void kernel_launch(void* const* d_in, const int* in_sizes, int n_in,
                              void* d_out, int out_size) {
    const float* preds   = (const float*)d_in[0];
    const float* targets = (const float*)d_in[1];
    const int*   lengths = (const int*)d_in[2];
    float* out = (float*)d_out;

    triplet_rows_kernel<<<NBLOCKS, WARPS_PER_BLOCK * 32>>>(preds, targets, lengths);
    finalize_kernel<<<1, 256>>>(lengths, out);
}

// round 2
// speedup vs baseline: 1.1628x; 1.1628x over previous
#include <cuda_runtime.h>

// SyntheticTripletLoss closed form: per valid row needs only
//   pp = <p,p>, tt = <t,t>, pt = <p,t>
//   sim_pn = (pp - pt^2) / max(sqrt(pp - 2pt^2 + pt^2*tt), EPS)
//   loss   = max(MARGIN + sim_pn - pt, 0);  mean over valid rows.
// Single fused kernel: streaming row pass + fence-and-ticket final reduce.

#define MARGIN 0.5f
#define EPS_N 1e-12f

static constexpr int B = 32;
static constexpr int T = 512;
static constexpr int D = 512;
static constexpr int WARPS_PER_BLOCK = 8;
static constexpr int THREADS = WARPS_PER_BLOCK * 32;    // 256
static constexpr int ROWS = B * T;                      // 16384
static constexpr int NBLOCKS = ROWS / WARPS_PER_BLOCK;  // 2048

__device__ float g_partials[NBLOCKS];
__device__ unsigned int g_ticket;  // zero-init; last block resets to 0 each run

__global__ __launch_bounds__(THREADS)
void triplet_fused_kernel(const float* __restrict__ preds,
                          const float* __restrict__ targets,
                          const int* __restrict__ lengths,
                          float* __restrict__ out) {
    const int warp = threadIdx.x >> 5;
    const int lane = threadIdx.x & 31;
    const int row  = blockIdx.x * WARPS_PER_BLOCK + warp;
    const int b    = row >> 9;        // row / T
    const int t    = row & (T - 1);   // row % T

    float loss = 0.0f;

    if (t < __ldg(&lengths[b])) {
        const float4* __restrict__ p4 =
            reinterpret_cast<const float4*>(preds + (size_t)row * D);
        const float4* __restrict__ t4 =
            reinterpret_cast<const float4*>(targets + (size_t)row * D);

        // 512 floats / 32 lanes = 4 float4 per lane per tensor; front-batch
        // all 8 loads for MLP.
        float4 a0 = __ldg(p4 + lane);
        float4 a1 = __ldg(p4 + lane + 32);
        float4 a2 = __ldg(p4 + lane + 64);
        float4 a3 = __ldg(p4 + lane + 96);
        float4 c0 = __ldg(t4 + lane);
        float4 c1 = __ldg(t4 + lane + 32);
        float4 c2 = __ldg(t4 + lane + 64);
        float4 c3 = __ldg(t4 + lane + 96);

        float pp = 0.f, tt = 0.f, pt = 0.f;
        #define ACC(a, c)                                                  \
            pp = fmaf(a.x, a.x, fmaf(a.y, a.y, fmaf(a.z, a.z, fmaf(a.w, a.w, pp)))); \
            tt = fmaf(c.x, c.x, fmaf(c.y, c.y, fmaf(c.z, c.z, fmaf(c.w, c.w, tt)))); \
            pt = fmaf(a.x, c.x, fmaf(a.y, c.y, fmaf(a.z, c.z, fmaf(a.w, c.w, pt))));
        ACC(a0, c0) ACC(a1, c1) ACC(a2, c2) ACC(a3, c3)
        #undef ACC

        #pragma unroll
        for (int off = 16; off; off >>= 1) {
            pp += __shfl_xor_sync(0xffffffffu, pp, off);
            tt += __shfl_xor_sync(0xffffffffu, tt, off);
            pt += __shfl_xor_sync(0xffffffffu, pt, off);
        }

        float pt2  = pt * pt;
        float n2   = fmaxf(pp - 2.0f * pt2 + pt2 * tt, 0.0f);
        float norm = fmaxf(sqrtf(n2), EPS_N);
        float sim_pn = (pp - pt2) / norm;
        loss = fmaxf(MARGIN + sim_pn - pt, 0.0f);
    }

    __shared__ float s_warp[WARPS_PER_BLOCK];
    __shared__ bool  s_is_last;
    if (lane == 0) s_warp[warp] = loss;
    __syncthreads();

    if (threadIdx.x == 0) {
        float sum = 0.f;
        #pragma unroll
        for (int i = 0; i < WARPS_PER_BLOCK; i++) sum += s_warp[i];
        g_partials[blockIdx.x] = sum;     // fixed slot: deterministic
        __threadfence();                  // make partial visible device-wide
        unsigned int ticket = atomicAdd(&g_ticket, 1u);
        s_is_last = (ticket == (unsigned int)(NBLOCKS - 1));
    }
    __syncthreads();

    if (!s_is_last) return;

    // Last block: all other partials are visible (their threadfence preceded
    // the ticket we observed). Reduce 2048 partials in fixed order.
    __shared__ float s_red[THREADS];
    float sum = 0.f;
    #pragma unroll
    for (int k = 0; k < NBLOCKS / THREADS; k++)
        sum += __ldcg(&g_partials[threadIdx.x + k * THREADS]);
    s_red[threadIdx.x] = sum;
    __syncthreads();
    #pragma unroll
    for (int off = THREADS / 2; off; off >>= 1) {
        if (threadIdx.x < off) s_red[threadIdx.x] += s_red[threadIdx.x + off];
        __syncthreads();
    }
    if (threadIdx.x == 0) {
        int cnt = 0;
        #pragma unroll
        for (int i = 0; i < B; i++) cnt += __ldg(&lengths[i]);
        out[0] = s_red[0] / (float)cnt;
        g_ticket = 0;                     // reset for next graph replay
    }
}

extern "C" void kernel_launch(void* const* d_in, const int* in_sizes, int n_in,
                              void* d_out, int out_size) {
    const float* preds   = (const float*)d_in[0];
    const float* targets = (const float*)d_in[1];
    const int*   lengths = (const int*)d_in[2];
    float* out = (float*)d_out;

    triplet_fused_kernel<<<NBLOCKS, THREADS>>>(preds, targets, lengths, out);
}